// round 7
// baseline (speedup 1.0000x reference)
#include <cuda_runtime.h>
#include <cuda_bf16.h>
#include <math.h>

#define B_SZ   16
#define C_IN   64
#define HH     256
#define WW     256
#define CKK    576
#define FC_DIM 512
#define IMG_PIX (HH * WW)
#define N_IMG  (B_SZ * C_IN)
#define FOUT_ELEMS ((size_t)N_IMG * IMG_PIX)

#define MLP_BLOCKS 64   // < 148 SMs -> all resident, spin barriers are safe

// Split-K partials (deterministic fixed-order summation)
__device__ float g_h_part[4][B_SZ * CKK];   // layer1 partials (kc0 includes b1)
__device__ float g_l_part[4][B_SZ * CKK];   // layer2 partials (kc0 includes b2)
__device__ float g_kw[B_SZ * CKK];          // softmaxed kernel weights
__device__ unsigned int g_cnt1, g_cnt2, g_cnt3;   // barrier counters (zero-init)

// Device-wide counter barrier. All MLP_BLOCKS blocks must be resident.
// If resetter != nullptr, the LAST arriver resets *resetter to 0 (safe:
// all blocks have passed the previous barrier by then).
__device__ __forceinline__ void grid_barrier(unsigned int* cnt, unsigned int* resetter) {
    __threadfence();
    __syncthreads();
    if (threadIdx.x == 0) {
        unsigned int old = atomicAdd(cnt, 1u);
        if (resetter && old == MLP_BLOCKS - 1u) *resetter = 0u;
        while (__ldcg(cnt) < MLP_BLOCKS) { }
    }
    __syncthreads();
    __threadfence();
}

// ---------------------------------------------------------------------------
// Fused MLP: one kernel, 64 blocks x 576 threads.
//  Phase 1: block (b*4+kc) -> 128-deep layer1 partial for all 576 j.
//  Phase 2: block (b*4+kc) -> 144-deep layer2 partial (h = relu(sum parts)).
//  Phase 3: blocks 0..15 -> softmax for batch b.
// ---------------------------------------------------------------------------
__global__ __launch_bounds__(CKK) void EKG_mlp_persistent(
    const float* __restrict__ Fc,
    const float* __restrict__ W1, const float* __restrict__ b1,
    const float* __restrict__ W2, const float* __restrict__ b2,
    float* __restrict__ kw_tail, int write_tail)
{
    __shared__ float sv[160];      // phase1: Fc slice (128); phase2: h slice (144)
    __shared__ float red[32];
    __shared__ float bcast;

    const int bid = blockIdx.x;
    const int b   = bid >> 2;
    const int kc  = bid & 3;
    const int j   = threadIdx.x;   // 0..575
    const int lane = j & 31;
    const int wid  = j >> 5;

    // ---------------- Phase 1: layer1 partial (128-deep) ----------------
    {
        const int i0 = kc * 128;
        if (j < 128) sv[j] = Fc[b * FC_DIM + i0 + j];
        __syncthreads();

        float a0 = 0.f, a1 = 0.f, a2 = 0.f, a3 = 0.f;
        const float* __restrict__ wp = W1 + (size_t)i0 * CKK + j;
        #pragma unroll
        for (int i = 0; i < 128; i += 4) {
            a0 = fmaf(sv[i + 0], wp[(i + 0) * CKK], a0);
            a1 = fmaf(sv[i + 1], wp[(i + 1) * CKK], a1);
            a2 = fmaf(sv[i + 2], wp[(i + 2) * CKK], a2);
            a3 = fmaf(sv[i + 3], wp[(i + 3) * CKK], a3);
        }
        float acc = (a0 + a1) + (a2 + a3);
        if (kc == 0) acc += b1[j];
        g_h_part[kc][b * CKK + j] = acc;
    }

    grid_barrier(&g_cnt1, 0);

    // ---------------- Phase 2: layer2 partial (144-deep) ----------------
    {
        const int i0 = kc * 144;
        __syncthreads();   // sv reuse
        if (j < 144) {
            const int idx = b * CKK + i0 + j;
            float h = ((g_h_part[0][idx] + g_h_part[1][idx]) +
                       (g_h_part[2][idx] + g_h_part[3][idx]));
            sv[j] = fmaxf(h, 0.0f);
        }
        __syncthreads();

        float a0 = 0.f, a1 = 0.f, a2 = 0.f, a3 = 0.f;
        const float* __restrict__ wp = W2 + (size_t)i0 * CKK + j;
        #pragma unroll
        for (int i = 0; i < 144; i += 4) {
            a0 = fmaf(sv[i + 0], wp[(i + 0) * CKK], a0);
            a1 = fmaf(sv[i + 1], wp[(i + 1) * CKK], a1);
            a2 = fmaf(sv[i + 2], wp[(i + 2) * CKK], a2);
            a3 = fmaf(sv[i + 3], wp[(i + 3) * CKK], a3);
        }
        float acc = (a0 + a1) + (a2 + a3);
        if (kc == 0) acc += b2[j];
        g_l_part[kc][b * CKK + j] = acc;
    }

    grid_barrier(&g_cnt2, &g_cnt1);   // last arriver resets cnt1 for next replay

    // ---------------- Phase 3: softmax (blocks 0..15) ----------------
    if (bid < B_SZ) {
        const int sb  = bid;
        const int idx = sb * CKK + j;
        const float logit = ((g_l_part[0][idx] + g_l_part[1][idx]) +
                             (g_l_part[2][idx] + g_l_part[3][idx]));

        float m = logit;
        #pragma unroll
        for (int o = 16; o > 0; o >>= 1)
            m = fmaxf(m, __shfl_xor_sync(0xffffffffu, m, o));
        if (lane == 0) red[wid] = m;
        __syncthreads();
        if (wid == 0) {
            float v = (lane < 18) ? red[lane] : -INFINITY;
            #pragma unroll
            for (int o = 16; o > 0; o >>= 1)
                v = fmaxf(v, __shfl_xor_sync(0xffffffffu, v, o));
            if (lane == 0) bcast = v;
        }
        __syncthreads();
        const float e = expf(logit - bcast);

        float s = e;
        #pragma unroll
        for (int o = 16; o > 0; o >>= 1)
            s += __shfl_xor_sync(0xffffffffu, s, o);
        __syncthreads();
        if (lane == 0) red[wid] = s;
        __syncthreads();
        if (wid == 0) {
            float v = (lane < 18) ? red[lane] : 0.0f;
            #pragma unroll
            for (int o = 16; o > 0; o >>= 1)
                v += __shfl_xor_sync(0xffffffffu, v, o);
            if (lane == 0) bcast = v;
        }
        __syncthreads();

        const float kw = e / bcast;
        g_kw[idx] = kw;
        if (write_tail) kw_tail[idx] = kw;
    }

    // Exit barrier (arrive-only): last arriver resets cnt2 and cnt3.
    __threadfence();
    __syncthreads();
    if (threadIdx.x == 0) {
        unsigned int old = atomicAdd(&g_cnt3, 1u);
        if (old == MLP_BLOCKS - 1u) { g_cnt2 = 0u; g_cnt3 = 0u; __threadfence(); }
    }
}

// ---------------------------------------------------------------------------
// Depthwise 3x3 conv, reflect pad, no smem (measured-best Round-3/5 config).
// Block 256: tx 0..63 (float4 col group), ty 0..3 (strip of 8 rows).
// Block tile 256x32. Grid (8, 1024).
// ---------------------------------------------------------------------------
#define ROWS_PER_BLOCK 32
#define ROWS_PER_THREAD 8

__device__ __forceinline__ void load_row6(
    const float* __restrict__ img, int gr, int tx, float* __restrict__ w)
{
    gr = (gr < 0) ? 1 : ((gr > HH - 1) ? (2 * HH - 2 - gr) : gr);
    const float* rowp = img + gr * WW;
    const float4 q = __ldg((const float4*)rowp + tx);
    w[1] = q.x; w[2] = q.y; w[3] = q.z; w[4] = q.w;
    w[0] = (tx == 0)      ? q.y : __ldg(rowp + 4 * tx - 1);
    w[5] = (tx == WW/4-1) ? q.z : __ldg(rowp + 4 * tx + 4);
}

__global__ __launch_bounds__(256) void EKG_conv_kernel(
    const float* __restrict__ Fd,
    float* __restrict__ out)
{
    const int bc   = blockIdx.y;
    const int tid  = threadIdx.x;
    const int tx   = tid & 63;
    const int ty   = tid >> 6;
    const int rbase = blockIdx.x * ROWS_PER_BLOCK + ty * ROWS_PER_THREAD;

    const float* __restrict__ img = Fd  + (size_t)bc * IMG_PIX;
    float*       __restrict__ o   = out + (size_t)bc * IMG_PIX;

    const float* kwp = g_kw + bc * 9;
    const float w00 = __ldg(kwp+0), w01 = __ldg(kwp+1), w02 = __ldg(kwp+2);
    const float w10 = __ldg(kwp+3), w11 = __ldg(kwp+4), w12 = __ldg(kwp+5);
    const float w20 = __ldg(kwp+6), w21 = __ldg(kwp+7), w22 = __ldg(kwp+8);

    float win[3][6];
    load_row6(img, rbase - 1, tx, win[0]);
    load_row6(img, rbase + 0, tx, win[1]);

    #pragma unroll
    for (int rr = 0; rr < ROWS_PER_THREAD; ++rr) {
        load_row6(img, rbase + rr + 1, tx, win[(rr + 2) % 3]);

        const float* T  = win[rr % 3];
        const float* M  = win[(rr + 1) % 3];
        const float* Bt = win[(rr + 2) % 3];

        float4 r;
        r.x = w00*T[0]; r.x = fmaf(w01,T[1],r.x); r.x = fmaf(w02,T[2],r.x);
        r.x = fmaf(w10,M[0],r.x); r.x = fmaf(w11,M[1],r.x); r.x = fmaf(w12,M[2],r.x);
        r.x = fmaf(w20,Bt[0],r.x); r.x = fmaf(w21,Bt[1],r.x); r.x = fmaf(w22,Bt[2],r.x);

        r.y = w00*T[1]; r.y = fmaf(w01,T[2],r.y); r.y = fmaf(w02,T[3],r.y);
        r.y = fmaf(w10,M[1],r.y); r.y = fmaf(w11,M[2],r.y); r.y = fmaf(w12,M[3],r.y);
        r.y = fmaf(w20,Bt[1],r.y); r.y = fmaf(w21,Bt[2],r.y); r.y = fmaf(w22,Bt[3],r.y);

        r.z = w00*T[2]; r.z = fmaf(w01,T[3],r.z); r.z = fmaf(w02,T[4],r.z);
        r.z = fmaf(w10,M[2],r.z); r.z = fmaf(w11,M[3],r.z); r.z = fmaf(w12,M[4],r.z);
        r.z = fmaf(w20,Bt[2],r.z); r.z = fmaf(w21,Bt[3],r.z); r.z = fmaf(w22,Bt[4],r.z);

        r.w = w00*T[3]; r.w = fmaf(w01,T[4],r.w); r.w = fmaf(w02,T[5],r.w);
        r.w = fmaf(w10,M[3],r.w); r.w = fmaf(w11,M[4],r.w); r.w = fmaf(w12,M[5],r.w);
        r.w = fmaf(w20,Bt[3],r.w); r.w = fmaf(w21,Bt[4],r.w); r.w = fmaf(w22,Bt[5],r.w);

        __stcs((float4*)(o + (size_t)(rbase + rr) * WW + 4 * tx), r);
    }
}

// ---------------------------------------------------------------------------
extern "C" void kernel_launch(void* const* d_in, const int* in_sizes, int n_in,
                              void* d_out, int out_size) {
    const float* Fd = (const float*)d_in[0];
    const float* Fc = (const float*)d_in[1];
    const float* W1 = (const float*)d_in[2];
    const float* b1 = (const float*)d_in[3];
    const float* W2 = (const float*)d_in[4];
    const float* b2 = (const float*)d_in[5];
    float* out = (float*)d_out;

    const int write_tail = ((size_t)out_size >= FOUT_ELEMS + (size_t)B_SZ * CKK) ? 1 : 0;
    float* kw_tail = out + FOUT_ELEMS;

    EKG_mlp_persistent<<<MLP_BLOCKS, CKK>>>(Fc, W1, b1, W2, b2, kw_tail, write_tail);

    dim3 grid(HH / ROWS_PER_BLOCK, N_IMG);
    EKG_conv_kernel<<<grid, 256>>>(Fd, out);
}

// round 8
// speedup vs baseline: 1.0161x; 1.0161x over previous
#include <cuda_runtime.h>
#include <cuda_bf16.h>
#include <math.h>

#define B_SZ   16
#define C_IN   64
#define HH     256
#define WW     256
#define CKK    576
#define FC_DIM 512
#define IMG_PIX (HH * WW)
#define N_IMG  (B_SZ * C_IN)
#define FOUT_ELEMS ((size_t)N_IMG * IMG_PIX)

#define MLP_BLOCKS 81   // < 148 SMs -> all resident; spin barriers safe

// Partial buffers (deterministic fixed-order summation)
__device__ float g_p1[8][B_SZ * CKK];   // layer1 partials per 64-i-chunk (ic0 includes b1)
__device__ float g_p2[9][B_SZ * CKK];   // layer2 partials per 64-i-chunk (ic0 includes b2)
__device__ float g_kw[B_SZ * CKK];      // softmaxed kernel weights
__device__ unsigned int g_c1, g_c2, g_c3;   // barrier counters (zero-init)

__device__ __forceinline__ void grid_barrier(unsigned int* cnt, unsigned int* rst) {
    __threadfence();
    __syncthreads();
    if (threadIdx.x == 0) {
        unsigned int old = atomicAdd(cnt, 1u);
        if (rst && old == MLP_BLOCKS - 1u) *rst = 0u;
        while (__ldcg(cnt) < MLP_BLOCKS) __nanosleep(20);
    }
    __syncthreads();
    __threadfence();
}

// ---------------------------------------------------------------------------
// One-kernel MLP, wide-parallel. 81 blocks x 256 threads.
//  Phase 1 (blocks 0..71 = jt*8+ic): W1 chunk [64i x 64j], all 16 batches.
//    Each thread: 16 independent W1 loads (W1 covered exactly once grid-wide),
//    acc[16] over batches from smem-broadcast Fc, ty-reduction in smem.
//  Phase 2 (all 81 = jt*9+ic): same over W2 with h = relu(sum of p1 parts).
//  Phase 3 (blocks 0..15): softmax per batch from p2 partials.
// ---------------------------------------------------------------------------
__global__ __launch_bounds__(256) void EKG_mlp_one(
    const float* __restrict__ Fc,
    const float* __restrict__ W1, const float* __restrict__ b1,
    const float* __restrict__ W2, const float* __restrict__ b2,
    float* __restrict__ kw_tail, int write_tail)
{
    __shared__ float sfc[16 * 64];        // [b][il] input slice
    __shared__ float srd[4 * 64 * 16];    // [ty][j_local][b] reduction buffer
    __shared__ float red[8];
    __shared__ float bcast;

    const int bid = blockIdx.x;
    const int tid = threadIdx.x;
    const int tx  = tid & 63;             // j within tile
    const int ty  = tid >> 6;             // i sub-chunk (16 deep)
    const int lane = tid & 31;
    const int wid  = tid >> 5;

    // ---------------- Phase 1 ----------------
    if (bid < 72) {
        const int jt = bid / 8, ic = bid % 8;
        const int i0 = ic * 64;
        const int j  = jt * 64 + tx;

        for (int q = tid; q < 16 * 64; q += 256) {
            const int b = q >> 6, il = q & 63;
            sfc[q] = Fc[b * FC_DIM + i0 + il];
        }
        __syncthreads();

        float w[16];
        const float* __restrict__ wp = W1 + (size_t)(i0 + ty * 16) * CKK + j;
        #pragma unroll
        for (int k = 0; k < 16; ++k) w[k] = __ldg(wp + k * CKK);

        float acc[16];
        #pragma unroll
        for (int b = 0; b < 16; ++b) acc[b] = 0.f;
        #pragma unroll
        for (int k = 0; k < 16; ++k) {
            const int il = ty * 16 + k;
            #pragma unroll
            for (int b = 0; b < 16; ++b)
                acc[b] = fmaf(sfc[b * 64 + il], w[k], acc[b]);
        }
        #pragma unroll
        for (int b = 0; b < 16; ++b) srd[(ty * 64 + tx) * 16 + b] = acc[b];
        __syncthreads();

        for (int q = tid; q < 1024; q += 256) {
            const int jj = q >> 4, b = q & 15;
            float v = ((srd[(jj) * 16 + b]       + srd[(64 + jj) * 16 + b]) +
                       (srd[(128 + jj) * 16 + b] + srd[(192 + jj) * 16 + b]));
            if (ic == 0) v += b1[jt * 64 + jj];
            g_p1[ic][b * CKK + jt * 64 + jj] = v;
        }
    }

    grid_barrier(&g_c1, 0);

    // ---------------- Phase 2 ----------------
    {
        const int jt = bid / 9, ic = bid % 9;
        const int i0 = ic * 64;
        const int j  = jt * 64 + tx;

        for (int q = tid; q < 16 * 64; q += 256) {
            const int b = q >> 6, il = q & 63;
            const int idx = b * CKK + i0 + il;
            float h = (((g_p1[0][idx] + g_p1[1][idx]) + (g_p1[2][idx] + g_p1[3][idx])) +
                       ((g_p1[4][idx] + g_p1[5][idx]) + (g_p1[6][idx] + g_p1[7][idx])));
            sfc[q] = fmaxf(h, 0.0f);
        }
        __syncthreads();

        float w[16];
        const float* __restrict__ wp = W2 + (size_t)(i0 + ty * 16) * CKK + j;
        #pragma unroll
        for (int k = 0; k < 16; ++k) w[k] = __ldg(wp + k * CKK);

        float acc[16];
        #pragma unroll
        for (int b = 0; b < 16; ++b) acc[b] = 0.f;
        #pragma unroll
        for (int k = 0; k < 16; ++k) {
            const int il = ty * 16 + k;
            #pragma unroll
            for (int b = 0; b < 16; ++b)
                acc[b] = fmaf(sfc[b * 64 + il], w[k], acc[b]);
        }
        __syncthreads();   // sfc/srd reuse safety within phase
        #pragma unroll
        for (int b = 0; b < 16; ++b) srd[(ty * 64 + tx) * 16 + b] = acc[b];
        __syncthreads();

        for (int q = tid; q < 1024; q += 256) {
            const int jj = q >> 4, b = q & 15;
            float v = ((srd[(jj) * 16 + b]       + srd[(64 + jj) * 16 + b]) +
                       (srd[(128 + jj) * 16 + b] + srd[(192 + jj) * 16 + b]));
            if (ic == 0) v += b2[jt * 64 + jj];
            g_p2[ic][b * CKK + jt * 64 + jj] = v;
        }
    }

    grid_barrier(&g_c2, &g_c1);   // last arriver resets c1 for next replay

    // ---------------- Phase 3: softmax (blocks 0..15) ----------------
    if (bid < B_SZ) {
        const int b = bid;
        // thread handles j = tid, tid+256, and tid+512 (only tid<64)
        float lg[3];
        float lmax = -INFINITY;
        #pragma unroll
        for (int t = 0; t < 3; ++t) {
            const int j = tid + 256 * t;
            if (t < 2 || tid < 64) {
                const int idx = b * CKK + j;
                float v = (((g_p2[0][idx] + g_p2[1][idx]) + (g_p2[2][idx] + g_p2[3][idx])) +
                           ((g_p2[4][idx] + g_p2[5][idx]) + (g_p2[6][idx] + g_p2[7][idx])) +
                           g_p2[8][idx]);
                lg[t] = v;
                lmax = fmaxf(lmax, v);
            } else lg[t] = -INFINITY;
        }
        #pragma unroll
        for (int o = 16; o > 0; o >>= 1)
            lmax = fmaxf(lmax, __shfl_xor_sync(0xffffffffu, lmax, o));
        if (lane == 0) red[wid] = lmax;
        __syncthreads();
        if (wid == 0) {
            float v = (lane < 8) ? red[lane] : -INFINITY;
            #pragma unroll
            for (int o = 4; o > 0; o >>= 1)
                v = fmaxf(v, __shfl_xor_sync(0xffffffffu, v, o));
            if (lane == 0) bcast = v;
        }
        __syncthreads();
        const float maxv = bcast;

        float e[3];
        float lsum = 0.f;
        #pragma unroll
        for (int t = 0; t < 3; ++t) {
            e[t] = (t < 2 || tid < 64) ? expf(lg[t] - maxv) : 0.0f;
            lsum += e[t];
        }
        #pragma unroll
        for (int o = 16; o > 0; o >>= 1)
            lsum += __shfl_xor_sync(0xffffffffu, lsum, o);
        __syncthreads();
        if (lane == 0) red[wid] = lsum;
        __syncthreads();
        if (wid == 0) {
            float v = (lane < 8) ? red[lane] : 0.0f;
            #pragma unroll
            for (int o = 4; o > 0; o >>= 1)
                v += __shfl_xor_sync(0xffffffffu, v, o);
            if (lane == 0) bcast = v;
        }
        __syncthreads();
        const float inv = 1.0f / bcast;

        #pragma unroll
        for (int t = 0; t < 3; ++t) {
            if (t < 2 || tid < 64) {
                const int idx = b * CKK + tid + 256 * t;
                const float kw = e[t] * inv;
                g_kw[idx] = kw;
                if (write_tail) kw_tail[idx] = kw;
            }
        }
    }

    // Exit barrier (arrive-only): last arriver resets c2 and c3.
    __threadfence();
    __syncthreads();
    if (tid == 0) {
        unsigned int old = atomicAdd(&g_c3, 1u);
        if (old == MLP_BLOCKS - 1u) { g_c2 = 0u; g_c3 = 0u; __threadfence(); }
    }
}

// ---------------------------------------------------------------------------
// Depthwise 3x3 conv, reflect pad, no smem (measured-best config, R3/R5).
// Block 256: tx 0..63 (float4 col group), ty 0..3 (strip of 8 rows).
// Block tile 256x32. Grid (8, 1024).
// ---------------------------------------------------------------------------
#define ROWS_PER_BLOCK 32
#define ROWS_PER_THREAD 8

__device__ __forceinline__ void load_row6(
    const float* __restrict__ img, int gr, int tx, float* __restrict__ w)
{
    gr = (gr < 0) ? 1 : ((gr > HH - 1) ? (2 * HH - 2 - gr) : gr);
    const float* rowp = img + gr * WW;
    const float4 q = __ldg((const float4*)rowp + tx);
    w[1] = q.x; w[2] = q.y; w[3] = q.z; w[4] = q.w;
    w[0] = (tx == 0)      ? q.y : __ldg(rowp + 4 * tx - 1);
    w[5] = (tx == WW/4-1) ? q.z : __ldg(rowp + 4 * tx + 4);
}

__global__ __launch_bounds__(256) void EKG_conv_kernel(
    const float* __restrict__ Fd,
    float* __restrict__ out)
{
    const int bc   = blockIdx.y;
    const int tid  = threadIdx.x;
    const int tx   = tid & 63;
    const int ty   = tid >> 6;
    const int rbase = blockIdx.x * ROWS_PER_BLOCK + ty * ROWS_PER_THREAD;

    const float* __restrict__ img = Fd  + (size_t)bc * IMG_PIX;
    float*       __restrict__ o   = out + (size_t)bc * IMG_PIX;

    const float* kwp = g_kw + bc * 9;
    const float w00 = __ldg(kwp+0), w01 = __ldg(kwp+1), w02 = __ldg(kwp+2);
    const float w10 = __ldg(kwp+3), w11 = __ldg(kwp+4), w12 = __ldg(kwp+5);
    const float w20 = __ldg(kwp+6), w21 = __ldg(kwp+7), w22 = __ldg(kwp+8);

    float win[3][6];
    load_row6(img, rbase - 1, tx, win[0]);
    load_row6(img, rbase + 0, tx, win[1]);

    #pragma unroll
    for (int rr = 0; rr < ROWS_PER_THREAD; ++rr) {
        load_row6(img, rbase + rr + 1, tx, win[(rr + 2) % 3]);

        const float* T  = win[rr % 3];
        const float* M  = win[(rr + 1) % 3];
        const float* Bt = win[(rr + 2) % 3];

        float4 r;
        r.x = w00*T[0]; r.x = fmaf(w01,T[1],r.x); r.x = fmaf(w02,T[2],r.x);
        r.x = fmaf(w10,M[0],r.x); r.x = fmaf(w11,M[1],r.x); r.x = fmaf(w12,M[2],r.x);
        r.x = fmaf(w20,Bt[0],r.x); r.x = fmaf(w21,Bt[1],r.x); r.x = fmaf(w22,Bt[2],r.x);

        r.y = w00*T[1]; r.y = fmaf(w01,T[2],r.y); r.y = fmaf(w02,T[3],r.y);
        r.y = fmaf(w10,M[1],r.y); r.y = fmaf(w11,M[2],r.y); r.y = fmaf(w12,M[3],r.y);
        r.y = fmaf(w20,Bt[1],r.y); r.y = fmaf(w21,Bt[2],r.y); r.y = fmaf(w22,Bt[3],r.y);

        r.z = w00*T[2]; r.z = fmaf(w01,T[3],r.z); r.z = fmaf(w02,T[4],r.z);
        r.z = fmaf(w10,M[2],r.z); r.z = fmaf(w11,M[3],r.z); r.z = fmaf(w12,M[4],r.z);
        r.z = fmaf(w20,Bt[2],r.z); r.z = fmaf(w21,Bt[3],r.z); r.z = fmaf(w22,Bt[4],r.z);

        r.w = w00*T[3]; r.w = fmaf(w01,T[4],r.w); r.w = fmaf(w02,T[5],r.w);
        r.w = fmaf(w10,M[3],r.w); r.w = fmaf(w11,M[4],r.w); r.w = fmaf(w12,M[5],r.w);
        r.w = fmaf(w20,Bt[3],r.w); r.w = fmaf(w21,Bt[4],r.w); r.w = fmaf(w22,Bt[5],r.w);

        __stcs((float4*)(o + (size_t)(rbase + rr) * WW + 4 * tx), r);
    }
}

// ---------------------------------------------------------------------------
extern "C" void kernel_launch(void* const* d_in, const int* in_sizes, int n_in,
                              void* d_out, int out_size) {
    const float* Fd = (const float*)d_in[0];
    const float* Fc = (const float*)d_in[1];
    const float* W1 = (const float*)d_in[2];
    const float* b1 = (const float*)d_in[3];
    const float* W2 = (const float*)d_in[4];
    const float* b2 = (const float*)d_in[5];
    float* out = (float*)d_out;

    const int write_tail = ((size_t)out_size >= FOUT_ELEMS + (size_t)B_SZ * CKK) ? 1 : 0;
    float* kw_tail = out + FOUT_ELEMS;

    EKG_mlp_one<<<MLP_BLOCKS, 256>>>(Fc, W1, b1, W2, b2, kw_tail, write_tail);

    dim3 grid(HH / ROWS_PER_BLOCK, N_IMG);
    EKG_conv_kernel<<<grid, 256>>>(Fd, out);
}